// round 5
// baseline (speedup 1.0000x reference)
#include <cuda_runtime.h>
#include <cstddef>

#define NTOK 65536  // 16 * 64 * 64 tokens

// ---------------- scratch (no allocations allowed) ----------------
__device__ float g_xn   [(size_t)NTOK * 256];   // LN1 + windowed, token-major
__device__ float g_qkv  [(size_t)NTOK * 768];
__device__ float g_attn [(size_t)NTOK * 256];
__device__ float g_tmp  [(size_t)NTOK * 256];
__device__ float g_attn2[(size_t)NTOK * 256];
__device__ float g_y    [(size_t)NTOK * 256];
__device__ float g_z    [(size_t)NTOK * 256];
__device__ float g_h1   [(size_t)NTOK * 1024];
__device__ float g_mlp  [(size_t)NTOK * 256];

// Token T (window order, shifted coords) -> original (b,h,w)
// T = ((b*8+wh)*8+ww)*64 + i*8+j ; shifted h' = wh*8+i ; orig h = (h'+4)&63
__device__ __forceinline__ void token_to_src(int T, int& b, int& h, int& w) {
    b = T >> 12;
    int rem = T & 4095;
    int winb = rem >> 6, pos = rem & 63;
    h = (((winb >> 3) << 3) + (pos >> 3) + 4) & 63;
    w = (((winb & 7) << 3) + (pos & 7) + 4) & 63;
}

// ---------------- kernel 1: LN1 + shift + window partition ----------------
// one warp per token; channels c = k*32+lane
__global__ void ln1_part(const float* __restrict__ x,
                         const float* __restrict__ g, const float* __restrict__ bb,
                         float* __restrict__ out) {
    int T = (blockIdx.x * 256 + threadIdx.x) >> 5;
    int lane = threadIdx.x & 31;
    int b, h, w; token_to_src(T, b, h, w);
    size_t xbase = (size_t)b * 1048576 + h * 64 + w;
    float v[8]; float s = 0.f;
#pragma unroll
    for (int k = 0; k < 8; k++) {
        v[k] = x[xbase + (size_t)(k * 32 + lane) * 4096];
        s += v[k];
    }
#pragma unroll
    for (int o = 16; o; o >>= 1) s += __shfl_xor_sync(0xffffffffu, s, o);
    float mu = s * 0.00390625f;
    float q = 0.f;
#pragma unroll
    for (int k = 0; k < 8; k++) { float d = v[k] - mu; q += d * d; }
#pragma unroll
    for (int o = 16; o; o >>= 1) q += __shfl_xor_sync(0xffffffffu, q, o);
    float rs = rsqrtf(q * 0.00390625f + 1e-6f);
    size_t tb = (size_t)T * 256;
#pragma unroll
    for (int k = 0; k < 8; k++) {
        int c = k * 32 + lane;
        out[tb + c] = (v[k] - mu) * rs * g[c] + bb[c];
    }
}

// ---------------- SGEMM: C[M,N] = A[M,K] @ B[N,K]^T + bias, optional GELU ----
// BM=BN=128, BK=8, TM=TN=8, 256 threads. All dims divisible (M=65536; N,K in {256,768,1024}).
template <bool GELU>
__global__ __launch_bounds__(256)
void sgemm(const float* __restrict__ A, const float* __restrict__ B,
           const float* __restrict__ bias, float* __restrict__ C,
           int M, int N, int K) {
    __shared__ float As[8][128];
    __shared__ float Bs[8][128];
    int bm = blockIdx.y * 128, bn = blockIdx.x * 128;
    int tid = threadIdx.x;
    int arow = tid >> 1, acol = (tid & 1) * 4;  // A: 128 rows x 8 k
    int ty = tid >> 4, tx = tid & 15;
    float acc[8][8];
#pragma unroll
    for (int i = 0; i < 8; i++)
#pragma unroll
        for (int j = 0; j < 8; j++) acc[i][j] = 0.f;

    const float* Ap = A + (size_t)(bm + arow) * K + acol;
    const float* Bp = B + (size_t)(bn + arow) * K + acol;

    for (int k0 = 0; k0 < K; k0 += 8) {
        float4 av = *(const float4*)(Ap + k0);
        float4 bv = *(const float4*)(Bp + k0);
        __syncthreads();
        As[acol + 0][arow] = av.x; As[acol + 1][arow] = av.y;
        As[acol + 2][arow] = av.z; As[acol + 3][arow] = av.w;
        Bs[acol + 0][arow] = bv.x; Bs[acol + 1][arow] = bv.y;
        Bs[acol + 2][arow] = bv.z; Bs[acol + 3][arow] = bv.w;
        __syncthreads();
#pragma unroll
        for (int k = 0; k < 8; ++k) {
            float4 a0 = *(const float4*)&As[k][ty * 8];
            float4 a1 = *(const float4*)&As[k][ty * 8 + 4];
            float4 b0 = *(const float4*)&Bs[k][tx * 8];
            float4 b1 = *(const float4*)&Bs[k][tx * 8 + 4];
            float ar[8] = {a0.x, a0.y, a0.z, a0.w, a1.x, a1.y, a1.z, a1.w};
            float br[8] = {b0.x, b0.y, b0.z, b0.w, b1.x, b1.y, b1.z, b1.w};
#pragma unroll
            for (int i = 0; i < 8; i++)
#pragma unroll
                for (int j = 0; j < 8; j++) acc[i][j] += ar[i] * br[j];
        }
    }
#pragma unroll
    for (int i = 0; i < 8; i++) {
        size_t row = (size_t)(bm + ty * 8 + i) * N;
#pragma unroll
        for (int j = 0; j < 8; j++) {
            int col = bn + tx * 8 + j;
            float v = acc[i][j] + bias[col];
            if (GELU) v = v * normcdff(v);  // exact gelu: x * Phi(x)
            C[row + col] = v;
        }
    }
}

// ---------------- attention: one block per (window, head) ----------------
__global__ __launch_bounds__(256)
void attn_kernel(const float* __restrict__ qkv, float* __restrict__ out) {
    __shared__ float Qs[64][33], Ks[64][33], Vs[64][33];
    __shared__ float S[64][65];
    __shared__ float rinv[64];
    int win = blockIdx.x, head = blockIdx.y;
    int tid = threadIdx.x;
    size_t base = (size_t)win * 64 * 768 + head * 32;
#pragma unroll
    for (int e = tid; e < 2048; e += 256) {
        int i = e >> 5, d = e & 31;
        size_t row = base + (size_t)i * 768 + d;
        Qs[i][d] = qkv[row];
        Ks[i][d] = qkv[row + 256];
        Vs[i][d] = qkv[row + 512];
    }
    __syncthreads();
    const float scale = 0.17677669529663687f;  // 1/sqrt(32)
#pragma unroll
    for (int e = tid; e < 4096; e += 256) {
        int i = e >> 6, j = e & 63;
        float s = 0.f;
#pragma unroll
        for (int d = 0; d < 32; ++d) s += Qs[i][d] * Ks[j][d];
        S[i][j] = s * scale;
    }
    __syncthreads();
    if (tid < 64) {
        float m = -1e30f;
        for (int j = 0; j < 64; ++j) m = fmaxf(m, S[tid][j]);
        float sum = 0.f;
        for (int j = 0; j < 64; ++j) { float e = expf(S[tid][j] - m); S[tid][j] = e; sum += e; }
        rinv[tid] = 1.f / sum;
    }
    __syncthreads();
#pragma unroll
    for (int e = tid; e < 2048; e += 256) {
        int i = e >> 5, d = e & 31;
        float s = 0.f;
#pragma unroll
        for (int j = 0; j < 64; ++j) s += S[i][j] * Vs[j][d];
        out[(size_t)(win * 64 + i) * 256 + head * 32 + d] = s * rinv[i];
    }
}

// ---------------- kernel 6: window reverse + residual + LN2 ----------------
__global__ void resid_ln2(const float* __restrict__ x, const float* __restrict__ a,
                          const float* __restrict__ g, const float* __restrict__ bb,
                          float* __restrict__ yout, float* __restrict__ zout) {
    int T = (blockIdx.x * 256 + threadIdx.x) >> 5;
    int lane = threadIdx.x & 31;
    int b, h, w; token_to_src(T, b, h, w);
    size_t xbase = (size_t)b * 1048576 + h * 64 + w;
    size_t tb = (size_t)T * 256;
    float v[8]; float s = 0.f;
#pragma unroll
    for (int k = 0; k < 8; k++) {
        int c = k * 32 + lane;
        v[k] = x[xbase + (size_t)c * 4096] + a[tb + c];
        s += v[k];
    }
#pragma unroll
    for (int o = 16; o; o >>= 1) s += __shfl_xor_sync(0xffffffffu, s, o);
    float mu = s * 0.00390625f;
    float q = 0.f;
#pragma unroll
    for (int k = 0; k < 8; k++) { float d = v[k] - mu; q += d * d; }
#pragma unroll
    for (int o = 16; o; o >>= 1) q += __shfl_xor_sync(0xffffffffu, q, o);
    float rs = rsqrtf(q * 0.00390625f + 1e-6f);
#pragma unroll
    for (int k = 0; k < 8; k++) {
        int c = k * 32 + lane;
        yout[tb + c] = v[k];
        zout[tb + c] = (v[k] - mu) * rs * g[c] + bb[c];
    }
}

// ---------------- final: out[b,c,h,w] = y_tok + mlp_tok (coalesced writes) ----
__global__ void final_add(const float* __restrict__ y, const float* __restrict__ m,
                          float* __restrict__ out) {
    size_t idx = (size_t)blockIdx.x * 256 + threadIdx.x;
    int w = (int)(idx & 63), h = (int)((idx >> 6) & 63);
    int c = (int)((idx >> 12) & 255), b = (int)(idx >> 20);
    int hp = (h + 60) & 63, wp = (w + 60) & 63;  // shifted coords
    int T = ((b * 8 + (hp >> 3)) * 8 + (wp >> 3)) * 64 + (hp & 7) * 8 + (wp & 7);
    size_t ti = (size_t)T * 256 + c;
    out[idx] = y[ti] + m[ti];
}

// ---------------- launch ----------------
extern "C" void kernel_launch(void* const* d_in, const int* in_sizes, int n_in,
                              void* d_out, int out_size) {
    const float* x      = (const float*)d_in[0];
    const float* n1g    = (const float*)d_in[1];
    const float* n1b    = (const float*)d_in[2];
    const float* in_w   = (const float*)d_in[3];
    const float* in_b   = (const float*)d_in[4];
    const float* out_w  = (const float*)d_in[5];
    const float* out_b  = (const float*)d_in[6];
    const float* proj_w = (const float*)d_in[7];
    const float* proj_b = (const float*)d_in[8];
    const float* n2g    = (const float*)d_in[9];
    const float* n2b    = (const float*)d_in[10];
    const float* fc1_w  = (const float*)d_in[11];
    const float* fc1_b  = (const float*)d_in[12];
    const float* fc2_w  = (const float*)d_in[13];
    const float* fc2_b  = (const float*)d_in[14];
    float* out = (float*)d_out;

    float *xn, *qkv, *attn, *tmp, *attn2, *yb, *zb, *h1, *mlp;
    cudaGetSymbolAddress((void**)&xn,    g_xn);
    cudaGetSymbolAddress((void**)&qkv,   g_qkv);
    cudaGetSymbolAddress((void**)&attn,  g_attn);
    cudaGetSymbolAddress((void**)&tmp,   g_tmp);
    cudaGetSymbolAddress((void**)&attn2, g_attn2);
    cudaGetSymbolAddress((void**)&yb,    g_y);
    cudaGetSymbolAddress((void**)&zb,    g_z);
    cudaGetSymbolAddress((void**)&h1,    g_h1);
    cudaGetSymbolAddress((void**)&mlp,   g_mlp);

    ln1_part<<<NTOK / 8, 256>>>(x, n1g, n1b, xn);
    sgemm<false><<<dim3(6, 512), 256>>>(xn, in_w, in_b, qkv, NTOK, 768, 256);
    attn_kernel<<<dim3(1024, 8), 256>>>(qkv, attn);
    sgemm<false><<<dim3(2, 512), 256>>>(attn, out_w, out_b, tmp, NTOK, 256, 256);
    sgemm<false><<<dim3(2, 512), 256>>>(tmp, proj_w, proj_b, attn2, NTOK, 256, 256);
    resid_ln2<<<NTOK / 8, 256>>>(x, attn2, n2g, n2b, yb, zb);
    sgemm<true ><<<dim3(8, 512), 256>>>(zb, fc1_w, fc1_b, h1, NTOK, 1024, 256);
    sgemm<false><<<dim3(2, 512), 256>>>(h1, fc2_w, fc2_b, mlp, NTOK, 256, 1024);
    final_add<<<NTOK, 256>>>(yb, mlp, out);
}

// round 7
// speedup vs baseline: 2.0457x; 2.0457x over previous
#include <cuda_runtime.h>
#include <cuda_bf16.h>
#include <cstdint>
#include <cstddef>

#define NTOK 65536  // 16 * 64 * 64 tokens

// ---------------- scratch (no allocations allowed) ----------------
__device__ __nv_bfloat16 g_xn_h [(size_t)NTOK * 256];
__device__ __nv_bfloat16 g_xn_l [(size_t)NTOK * 256];
__device__ float         g_qkv  [(size_t)NTOK * 768];
__device__ __nv_bfloat16 g_at_h [(size_t)NTOK * 256];
__device__ __nv_bfloat16 g_at_l [(size_t)NTOK * 256];
__device__ __nv_bfloat16 g_tmp_h[(size_t)NTOK * 256];
__device__ __nv_bfloat16 g_tmp_l[(size_t)NTOK * 256];
__device__ float         g_attn2[(size_t)NTOK * 256];
__device__ float         g_y    [(size_t)NTOK * 256];
__device__ __nv_bfloat16 g_z_h  [(size_t)NTOK * 256];
__device__ __nv_bfloat16 g_z_l  [(size_t)NTOK * 256];
__device__ __nv_bfloat16 g_h1_h [(size_t)NTOK * 1024];
__device__ __nv_bfloat16 g_h1_l [(size_t)NTOK * 1024];
__device__ float         g_mlp  [(size_t)NTOK * 256];
// packed bf16 hi/lo weights: in_w(196608) out_w(65536) proj_w(65536) fc1_w(262144) fc2_w(262144)
__device__ __nv_bfloat16 g_w_h[851968];
__device__ __nv_bfloat16 g_w_l[851968];

#define OFF_INW  0
#define OFF_OUTW 196608
#define OFF_PRJW 262144
#define OFF_FC1W 327680
#define OFF_FC2W 589824

// ---------------- small helpers ----------------
__device__ __forceinline__ void split2(float v, __nv_bfloat16& h, __nv_bfloat16& l) {
    h = __float2bfloat16(v);
    l = __float2bfloat16(v - __bfloat162float(h));
}

__device__ __forceinline__ uint32_t smem_u32(const void* p) {
    uint32_t a;
    asm("{ .reg .u64 t; cvta.to.shared.u64 t, %1; cvt.u32.u64 %0, t; }" : "=r"(a) : "l"(p));
    return a;
}

#define CPA16(dst, src) \
    asm volatile("cp.async.cg.shared.global [%0], [%1], 16;\n" :: "r"(dst), "l"(src))
#define CPA_COMMIT() asm volatile("cp.async.commit_group;\n" ::: "memory")
#define CPA_WAIT1()  asm volatile("cp.async.wait_group 1;\n" ::: "memory")
#define CPA_WAIT0()  asm volatile("cp.async.wait_group 0;\n" ::: "memory")

__device__ __forceinline__ void ldsm4(uint32_t* r, uint32_t addr) {
    asm volatile("ldmatrix.sync.aligned.m8n8.x4.shared.b16 {%0,%1,%2,%3}, [%4];\n"
                 : "=r"(r[0]), "=r"(r[1]), "=r"(r[2]), "=r"(r[3]) : "r"(addr));
}
__device__ __forceinline__ void mma16816(float* c, const uint32_t* a, uint32_t b0, uint32_t b1) {
    asm volatile(
        "mma.sync.aligned.m16n8k16.row.col.f32.bf16.bf16.f32 "
        "{%0,%1,%2,%3}, {%4,%5,%6,%7}, {%8,%9}, {%0,%1,%2,%3};\n"
        : "+f"(c[0]), "+f"(c[1]), "+f"(c[2]), "+f"(c[3])
        : "r"(a[0]), "r"(a[1]), "r"(a[2]), "r"(a[3]), "r"(b0), "r"(b1));
}

// ---------------- mma.sync split-bf16 GEMM ----------------
// C[M,N] = A[M,K] @ B[N,K]^T + bias, A/B as (hi,lo) bf16 pairs; 3-pass split.
// Block 128x128, 8 warps (2x4), warp tile 64x32, BK=32, cp.async double buffer.
// smem tile: 128 rows x 80B (64B data + 16B pad) -> ldmatrix conflict-free.
#define ROW_B       80
#define TILE_B      (128 * ROW_B)     // 10240
#define STAGE_B     (4 * TILE_B)      // Ah | Al | Bh | Bl = 40960
#define GEMM_SMEM   (2 * STAGE_B)     // 81920

template <int OUTMODE /*0=f32, 1=hilo*/, bool GELU>
__global__ __launch_bounds__(256)
void mma_gemm(const __nv_bfloat16* __restrict__ Ah, const __nv_bfloat16* __restrict__ Al,
              const __nv_bfloat16* __restrict__ Bh, const __nv_bfloat16* __restrict__ Bl,
              const float* __restrict__ bias,
              float* __restrict__ Cf,
              __nv_bfloat16* __restrict__ Ch, __nv_bfloat16* __restrict__ Cl,
              int N, int K) {
    extern __shared__ char smem[];
    const uint32_t sb0 = smem_u32(smem);
    const int tid = threadIdx.x, lane = tid & 31, wid = tid >> 5;
    const int wm = wid >> 2, wn = wid & 3;        // 2 x 4 warp grid
    const int bm = blockIdx.y * 128, bn = blockIdx.x * 128;

    float acc[4][4][4];
#pragma unroll
    for (int i = 0; i < 4; i++)
#pragma unroll
        for (int j = 0; j < 4; j++)
#pragma unroll
            for (int k = 0; k < 4; k++) acc[i][j][k] = 0.f;

    const int nc = K >> 5;  // BK=32 chunks

    auto load_stage = [&](int c, int s) {
        const uint32_t base = sb0 + s * STAGE_B;
        const size_t k0 = (size_t)c << 5;
#pragma unroll
        for (int it = 0; it < 2; ++it) {
            int e = it * 256 + tid;
            int row = e >> 2, ch = e & 3;
            uint32_t d = base + row * ROW_B + ch * 16;
            size_t ga = ((size_t)(bm + row) * K + k0 + ch * 8) * 2;
            size_t gb = ((size_t)(bn + row) * K + k0 + ch * 8) * 2;
            CPA16(d,              (const char*)Ah + ga);
            CPA16(d + TILE_B,     (const char*)Al + ga);
            CPA16(d + 2 * TILE_B, (const char*)Bh + gb);
            CPA16(d + 3 * TILE_B, (const char*)Bl + gb);
        }
        CPA_COMMIT();
    };

    load_stage(0, 0);

    // per-warp ldmatrix base offsets (within a tile)
    const uint32_t a_off = (uint32_t)((wm * 64 + (lane & 15)) * ROW_B + (lane >> 4) * 16);
    const uint32_t b_off = (uint32_t)((wn * 32 + (lane & 7) + ((lane >> 4) << 3)) * ROW_B +
                                      ((lane >> 3) & 1) * 16);

    for (int c = 0; c < nc; ++c) {
        const int s = c & 1;
        if (c + 1 < nc) { load_stage(c + 1, (c + 1) & 1); CPA_WAIT1(); }
        else            { CPA_WAIT0(); }
        __syncthreads();

        const uint32_t base = sb0 + s * STAGE_B;
        const uint32_t abase = base + a_off;
        const uint32_t bbase = base + 2 * TILE_B + b_off;
#pragma unroll
        for (int pass = 0; pass < 3; ++pass) {
            const uint32_t ab = abase + (pass == 2 ? TILE_B : 0);  // Al on pass2
            const uint32_t bb = bbase + (pass == 1 ? TILE_B : 0);  // Bl on pass1
#pragma unroll
            for (int ks = 0; ks < 2; ++ks) {
                uint32_t a[4][4], b[2][4];
#pragma unroll
                for (int mf = 0; mf < 4; ++mf) ldsm4(a[mf], ab + mf * 16 * ROW_B + ks * 32);
#pragma unroll
                for (int nf = 0; nf < 2; ++nf) ldsm4(b[nf], bb + nf * 16 * ROW_B + ks * 32);
#pragma unroll
                for (int mf = 0; mf < 4; ++mf)
#pragma unroll
                    for (int nf = 0; nf < 2; ++nf)
#pragma unroll
                        for (int sub = 0; sub < 2; ++sub)
                            mma16816(acc[mf][nf * 2 + sub], a[mf],
                                     b[nf][sub * 2], b[nf][sub * 2 + 1]);
            }
        }
        __syncthreads();
    }

    // epilogue straight from fragments: c0,c1 = (r, col..col+1); c2,c3 = (r+8, ...)
#pragma unroll
    for (int mf = 0; mf < 4; ++mf) {
#pragma unroll
        for (int nf8 = 0; nf8 < 4; ++nf8) {
            int row = bm + wm * 64 + mf * 16 + (lane >> 2);
            int col = bn + wn * 32 + nf8 * 8 + (lane & 3) * 2;
            float b0 = bias[col], b1 = bias[col + 1];
#pragma unroll
            for (int half = 0; half < 2; ++half) {
                int r = row + half * 8;
                float v0 = acc[mf][nf8][half * 2 + 0] + b0;
                float v1 = acc[mf][nf8][half * 2 + 1] + b1;
                if (GELU) { v0 = v0 * normcdff(v0); v1 = v1 * normcdff(v1); }
                size_t o = (size_t)r * N + col;
                if (OUTMODE == 0) {
                    *(float2*)(Cf + o) = make_float2(v0, v1);
                } else {
                    __nv_bfloat16 h0, l0, h1, l1;
                    split2(v0, h0, l0); split2(v1, h1, l1);
                    *(__nv_bfloat162*)(Ch + o) = __nv_bfloat162(h0, h1);
                    *(__nv_bfloat162*)(Cl + o) = __nv_bfloat162(l0, l1);
                }
            }
        }
    }
}

// ---------------- weight fp32 -> (hi,lo) bf16 ----------------
__global__ void cvtw(const float* __restrict__ w, __nv_bfloat16* __restrict__ h,
                     __nv_bfloat16* __restrict__ l, int n) {
    int i = blockIdx.x * 256 + threadIdx.x;
    if (i < n) {
        __nv_bfloat16 hh, ll;
        split2(w[i], hh, ll);
        h[i] = hh; l[i] = ll;
    }
}

// Token T (window order, shifted coords) -> original (b,h,w)
__device__ __forceinline__ void token_to_src(int T, int& b, int& h, int& w) {
    b = T >> 12;
    int rem = T & 4095;
    int winb = rem >> 6, pos = rem & 63;
    h = (((winb >> 3) << 3) + (pos >> 3) + 4) & 63;
    w = (((winb & 7) << 3) + (pos & 7) + 4) & 63;
}

// ---------------- LN1 + shift + window partition -> bf16 hi/lo ----------------
__global__ void ln1_part(const float* __restrict__ x,
                         const float* __restrict__ g, const float* __restrict__ bb,
                         __nv_bfloat16* __restrict__ oh, __nv_bfloat16* __restrict__ ol) {
    int T = (blockIdx.x * 256 + threadIdx.x) >> 5;
    int lane = threadIdx.x & 31;
    int b, h, w; token_to_src(T, b, h, w);
    size_t xbase = (size_t)b * 1048576 + h * 64 + w;
    float v[8]; float s = 0.f;
#pragma unroll
    for (int k = 0; k < 8; k++) {
        v[k] = x[xbase + (size_t)(k * 32 + lane) * 4096];
        s += v[k];
    }
#pragma unroll
    for (int o = 16; o; o >>= 1) s += __shfl_xor_sync(0xffffffffu, s, o);
    float mu = s * 0.00390625f;
    float q = 0.f;
#pragma unroll
    for (int k = 0; k < 8; k++) { float d = v[k] - mu; q += d * d; }
#pragma unroll
    for (int o = 16; o; o >>= 1) q += __shfl_xor_sync(0xffffffffu, q, o);
    float rs = rsqrtf(q * 0.00390625f + 1e-6f);
    size_t tb = (size_t)T * 256;
#pragma unroll
    for (int k = 0; k < 8; k++) {
        int c = k * 32 + lane;
        float val = (v[k] - mu) * rs * g[c] + bb[c];
        __nv_bfloat16 hh, ll; split2(val, hh, ll);
        oh[tb + c] = hh; ol[tb + c] = ll;
    }
}

// ---------------- attention: one block per (window, head) ----------------
__global__ __launch_bounds__(256)
void attn_kernel(const float* __restrict__ qkv,
                 __nv_bfloat16* __restrict__ oh, __nv_bfloat16* __restrict__ ol) {
    __shared__ float Qs[64][33], Ks[64][33], Vs[64][33];
    __shared__ float S[64][65];
    __shared__ float rinv[64];
    int win = blockIdx.x, head = blockIdx.y;
    int tid = threadIdx.x;
    size_t base = (size_t)win * 64 * 768 + head * 32;
#pragma unroll
    for (int e = tid; e < 2048; e += 256) {
        int i = e >> 5, d = e & 31;
        size_t row = base + (size_t)i * 768 + d;
        Qs[i][d] = qkv[row];
        Ks[i][d] = qkv[row + 256];
        Vs[i][d] = qkv[row + 512];
    }
    __syncthreads();
    const float scale = 0.17677669529663687f;  // 1/sqrt(32)
#pragma unroll
    for (int e = tid; e < 4096; e += 256) {
        int i = e >> 6, j = e & 63;
        float s = 0.f;
#pragma unroll
        for (int d = 0; d < 32; ++d) s += Qs[i][d] * Ks[j][d];
        S[i][j] = s * scale;
    }
    __syncthreads();
    if (tid < 64) {
        float m = -1e30f;
        for (int j = 0; j < 64; ++j) m = fmaxf(m, S[tid][j]);
        float sum = 0.f;
        for (int j = 0; j < 64; ++j) { float e = expf(S[tid][j] - m); S[tid][j] = e; sum += e; }
        rinv[tid] = 1.f / sum;
    }
    __syncthreads();
#pragma unroll
    for (int e = tid; e < 2048; e += 256) {
        int i = e >> 5, d = e & 31;
        float s = 0.f;
#pragma unroll
        for (int j = 0; j < 64; ++j) s += S[i][j] * Vs[j][d];
        float val = s * rinv[i];
        __nv_bfloat16 hh, ll; split2(val, hh, ll);
        size_t o = (size_t)(win * 64 + i) * 256 + head * 32 + d;
        oh[o] = hh; ol[o] = ll;
    }
}

// ---------------- window reverse + residual + LN2 ----------------
__global__ void resid_ln2(const float* __restrict__ x, const float* __restrict__ a,
                          const float* __restrict__ g, const float* __restrict__ bb,
                          float* __restrict__ yout,
                          __nv_bfloat16* __restrict__ zh, __nv_bfloat16* __restrict__ zl) {
    int T = (blockIdx.x * 256 + threadIdx.x) >> 5;
    int lane = threadIdx.x & 31;
    int b, h, w; token_to_src(T, b, h, w);
    size_t xbase = (size_t)b * 1048576 + h * 64 + w;
    size_t tb = (size_t)T * 256;
    float v[8]; float s = 0.f;
#pragma unroll
    for (int k = 0; k < 8; k++) {
        int c = k * 32 + lane;
        v[k] = x[xbase + (size_t)c * 4096] + a[tb + c];
        s += v[k];
    }
#pragma unroll
    for (int o = 16; o; o >>= 1) s += __shfl_xor_sync(0xffffffffu, s, o);
    float mu = s * 0.00390625f;
    float q = 0.f;
#pragma unroll
    for (int k = 0; k < 8; k++) { float d = v[k] - mu; q += d * d; }
#pragma unroll
    for (int o = 16; o; o >>= 1) q += __shfl_xor_sync(0xffffffffu, q, o);
    float rs = rsqrtf(q * 0.00390625f + 1e-6f);
#pragma unroll
    for (int k = 0; k < 8; k++) {
        int c = k * 32 + lane;
        yout[tb + c] = v[k];
        float val = (v[k] - mu) * rs * g[c] + bb[c];
        __nv_bfloat16 hh, ll; split2(val, hh, ll);
        zh[tb + c] = hh; zl[tb + c] = ll;
    }
}

// ---------------- final: out[b,c,h,w] = y_tok + mlp_tok ----------------
__global__ void final_add(const float* __restrict__ y, const float* __restrict__ m,
                          float* __restrict__ out) {
    size_t idx = (size_t)blockIdx.x * 256 + threadIdx.x;
    int w = (int)(idx & 63), h = (int)((idx >> 6) & 63);
    int c = (int)((idx >> 12) & 255), b = (int)(idx >> 20);
    int hp = (h + 60) & 63, wp = (w + 60) & 63;
    int T = ((b * 8 + (hp >> 3)) * 8 + (wp >> 3)) * 64 + (hp & 7) * 8 + (wp & 7);
    size_t ti = (size_t)T * 256 + c;
    out[idx] = y[ti] + m[ti];
}

// ---------------- launch ----------------
extern "C" void kernel_launch(void* const* d_in, const int* in_sizes, int n_in,
                              void* d_out, int out_size) {
    const float* x      = (const float*)d_in[0];
    const float* n1g    = (const float*)d_in[1];
    const float* n1b    = (const float*)d_in[2];
    const float* in_w   = (const float*)d_in[3];
    const float* in_b   = (const float*)d_in[4];
    const float* out_w  = (const float*)d_in[5];
    const float* out_b  = (const float*)d_in[6];
    const float* proj_w = (const float*)d_in[7];
    const float* proj_b = (const float*)d_in[8];
    const float* n2g    = (const float*)d_in[9];
    const float* n2b    = (const float*)d_in[10];
    const float* fc1_w  = (const float*)d_in[11];
    const float* fc1_b  = (const float*)d_in[12];
    const float* fc2_w  = (const float*)d_in[13];
    const float* fc2_b  = (const float*)d_in[14];
    float* out = (float*)d_out;

    __nv_bfloat16 *xnh, *xnl, *ath, *atl, *tmph, *tmpl, *zh, *zl, *h1h, *h1l, *wh, *wl;
    float *qkv, *attn2, *yb, *mlp;
    cudaGetSymbolAddress((void**)&xnh,   g_xn_h);
    cudaGetSymbolAddress((void**)&xnl,   g_xn_l);
    cudaGetSymbolAddress((void**)&qkv,   g_qkv);
    cudaGetSymbolAddress((void**)&ath,   g_at_h);
    cudaGetSymbolAddress((void**)&atl,   g_at_l);
    cudaGetSymbolAddress((void**)&tmph,  g_tmp_h);
    cudaGetSymbolAddress((void**)&tmpl,  g_tmp_l);
    cudaGetSymbolAddress((void**)&attn2, g_attn2);
    cudaGetSymbolAddress((void**)&yb,    g_y);
    cudaGetSymbolAddress((void**)&zh,    g_z_h);
    cudaGetSymbolAddress((void**)&zl,    g_z_l);
    cudaGetSymbolAddress((void**)&h1h,   g_h1_h);
    cudaGetSymbolAddress((void**)&h1l,   g_h1_l);
    cudaGetSymbolAddress((void**)&mlp,   g_mlp);
    cudaGetSymbolAddress((void**)&wh,    g_w_h);
    cudaGetSymbolAddress((void**)&wl,    g_w_l);

    cudaFuncSetAttribute(mma_gemm<0, false>, cudaFuncAttributeMaxDynamicSharedMemorySize, GEMM_SMEM);
    cudaFuncSetAttribute(mma_gemm<1, false>, cudaFuncAttributeMaxDynamicSharedMemorySize, GEMM_SMEM);
    cudaFuncSetAttribute(mma_gemm<1, true >, cudaFuncAttributeMaxDynamicSharedMemorySize, GEMM_SMEM);

    // weight conversion (deterministic, tiny)
    cvtw<<<768,  256>>>(in_w,   wh + OFF_INW,  wl + OFF_INW,  196608);
    cvtw<<<256,  256>>>(out_w,  wh + OFF_OUTW, wl + OFF_OUTW, 65536);
    cvtw<<<256,  256>>>(proj_w, wh + OFF_PRJW, wl + OFF_PRJW, 65536);
    cvtw<<<1024, 256>>>(fc1_w,  wh + OFF_FC1W, wl + OFF_FC1W, 262144);
    cvtw<<<1024, 256>>>(fc2_w,  wh + OFF_FC2W, wl + OFF_FC2W, 262144);

    ln1_part<<<NTOK / 8, 256>>>(x, n1g, n1b, xnh, xnl);

    // qkv: [65536,768] = xn @ in_w^T
    mma_gemm<0, false><<<dim3(6, 512), 256, GEMM_SMEM>>>(
        xnh, xnl, wh + OFF_INW, wl + OFF_INW, in_b, qkv, nullptr, nullptr, 768, 256);

    attn_kernel<<<dim3(1024, 8), 256>>>(qkv, ath, atl);

    // out_w: [65536,256]
    mma_gemm<1, false><<<dim3(2, 512), 256, GEMM_SMEM>>>(
        ath, atl, wh + OFF_OUTW, wl + OFF_OUTW, out_b, nullptr, tmph, tmpl, 256, 256);

    // proj_w: [65536,256]
    mma_gemm<0, false><<<dim3(2, 512), 256, GEMM_SMEM>>>(
        tmph, tmpl, wh + OFF_PRJW, wl + OFF_PRJW, proj_b, attn2, nullptr, nullptr, 256, 256);

    resid_ln2<<<NTOK / 8, 256>>>(x, attn2, n2g, n2b, yb, zh, zl);

    // fc1 + gelu: [65536,1024]
    mma_gemm<1, true><<<dim3(8, 512), 256, GEMM_SMEM>>>(
        zh, zl, wh + OFF_FC1W, wl + OFF_FC1W, fc1_b, nullptr, h1h, h1l, 1024, 256);

    // fc2: [65536,256], K=1024
    mma_gemm<0, false><<<dim3(2, 512), 256, GEMM_SMEM>>>(
        h1h, h1l, wh + OFF_FC2W, wl + OFF_FC2W, fc2_b, mlp, nullptr, nullptr, 256, 1024);

    final_add<<<NTOK, 256>>>(yb, mlp, out);
}